// round 2
// baseline (speedup 1.0000x reference)
#include <cuda_runtime.h>
#include <mma.h>
#include <math.h>

using namespace nvcuda;

#define BB 2
#define SS 2048
#define HH 16
#define DD 64
#define DIM 1024
#define MROWS (BB*SS)

__device__ float g_Q[BB*HH*SS*DD];
__device__ float g_K[BB*HH*SS*DD];
__device__ float g_V[BB*HH*SS*DD];
__device__ float g_O[MROWS*DIM];

// ---------------- cp.async helpers ----------------
__device__ __forceinline__ void cp16(void* s, const void* g) {
    unsigned saddr = (unsigned)__cvta_generic_to_shared(s);
    asm volatile("cp.async.cg.shared.global [%0], [%1], 16;\n" :: "r"(saddr), "l"(g));
}
__device__ __forceinline__ void cp_commit() { asm volatile("cp.async.commit_group;\n"); }
template<int N> __device__ __forceinline__ void cp_wait() {
    asm volatile("cp.async.wait_group %0;\n" :: "n"(N));
}

template<class F>
__device__ __forceinline__ void frag_to_tf32(F& f) {
#pragma unroll
    for (int t = 0; t < f.num_elements; t++) f.x[t] = wmma::__float_to_tf32(f.x[t]);
}

// ---------------------------------------------------------------------------
// Projection GEMM body: 128x128 tile, 256 threads, K-chunk 32, double-buffered.
// Warp grid 4x2: warp (wm,wn) computes rows wm*32..+32, cols wn*64..+64.
// ---------------------------------------------------------------------------
#define LDA 40
#define LDB 136

struct ProjAcc {
    wmma::fragment<wmma::accumulator,16,16,8,float> acc[2][4];
};

__device__ __forceinline__ void proj_mainloop(
    const float* __restrict__ X, const float* __restrict__ W,
    int m0, int n0, int tid, int wm, int wn,
    float* As0, float* As1, float* Bs0, float* Bs1, ProjAcc& P)
{
#pragma unroll
    for (int i = 0; i < 2; i++)
#pragma unroll
        for (int j = 0; j < 4; j++) wmma::fill_fragment(P.acc[i][j], 0.f);

    float* As[2] = {As0, As1};
    float* Bs[2] = {Bs0, Bs1};

    auto issue = [&](int k0, int buf) {
#pragma unroll
        for (int i = tid; i < 1024; i += 256) {         // A: 128x32
            int r = i >> 3, c = (i & 7) << 2;
            cp16(As[buf] + r*LDA + c, X + (size_t)(m0 + r)*DIM + k0 + c);
        }
#pragma unroll
        for (int i = tid; i < 1024; i += 256) {         // B: 32x128
            int r = i >> 5, c = (i & 31) << 2;
            cp16(Bs[buf] + r*LDB + c, W + (size_t)(k0 + r)*DIM + n0 + c);
        }
    };

    issue(0, 0); cp_commit();

    for (int it = 0; it < DIM/32; it++) {
        int buf = it & 1;
        if (it + 1 < DIM/32) { issue((it+1)*32, buf ^ 1); cp_commit(); cp_wait<1>(); }
        else                 { cp_wait<0>(); }
        __syncthreads();

#pragma unroll
        for (int kk = 0; kk < 4; kk++) {
            wmma::fragment<wmma::matrix_a,16,16,8,wmma::precision::tf32,wmma::row_major> a[2];
            wmma::fragment<wmma::matrix_b,16,16,8,wmma::precision::tf32,wmma::row_major> bfr[4];
#pragma unroll
            for (int i = 0; i < 2; i++) {
                wmma::load_matrix_sync(a[i], As[buf] + (wm*32 + i*16)*LDA + kk*8, LDA);
                frag_to_tf32(a[i]);
            }
#pragma unroll
            for (int j = 0; j < 4; j++) {
                wmma::load_matrix_sync(bfr[j], Bs[buf] + (kk*8)*LDB + wn*64 + j*16, LDB);
                frag_to_tf32(bfr[j]);
            }
#pragma unroll
            for (int i = 0; i < 2; i++)
#pragma unroll
                for (int j = 0; j < 4; j++)
                    wmma::mma_sync(P.acc[i][j], a[i], bfr[j], P.acc[i][j]);
        }
        __syncthreads();
    }
}

// QKV: scatter into (B,H,S,D). Warp col span (64) == one head exactly.
__global__ __launch_bounds__(256) void qkv_kernel(
    const float* __restrict__ x, const float* __restrict__ Wq,
    const float* __restrict__ Wk, const float* __restrict__ Wv)
{
    __shared__ float As0[128*LDA], As1[128*LDA];
    __shared__ float Bs0[32*LDB],  Bs1[32*LDB];

    const float* W; float* out;
    if (blockIdx.z == 0)      { W = Wq; out = g_Q; }
    else if (blockIdx.z == 1) { W = Wk; out = g_K; }
    else                      { W = Wv; out = g_V; }

    const int tid = threadIdx.x, wid = tid >> 5, wm = wid >> 1, wn = wid & 1;
    const int m0 = blockIdx.y * 128, n0 = blockIdx.x * 128;

    ProjAcc P;
    proj_mainloop(x, W, m0, n0, tid, wm, wn, As0, As1, Bs0, Bs1, P);

    const int bb = m0 >> 11, s0 = m0 & 2047;
    const int h  = (n0 >> 6) + wn;
    float* base = out + ((size_t)((bb << 4) + h) * SS + s0 + wm*32) * DD;
#pragma unroll
    for (int i = 0; i < 2; i++)
#pragma unroll
        for (int j = 0; j < 4; j++)
            wmma::store_matrix_sync(base + (i*16)*DD + j*16, P.acc[i][j], DD, wmma::mem_row_major);
}

__global__ __launch_bounds__(256) void oproj_kernel(
    const float* __restrict__ Wo, float* __restrict__ C)
{
    __shared__ float As0[128*LDA], As1[128*LDA];
    __shared__ float Bs0[32*LDB],  Bs1[32*LDB];

    const int tid = threadIdx.x, wid = tid >> 5, wm = wid >> 1, wn = wid & 1;
    const int m0 = blockIdx.y * 128, n0 = blockIdx.x * 128;

    ProjAcc P;
    proj_mainloop(g_O, Wo, m0, n0, tid, wm, wn, As0, As1, Bs0, Bs1, P);

    float* base = C + (size_t)(m0 + wm*32) * DIM + n0 + wn*64;
#pragma unroll
    for (int i = 0; i < 2; i++)
#pragma unroll
        for (int j = 0; j < 4; j++)
            wmma::store_matrix_sync(base + (size_t)(i*16)*DIM + j*16, P.acc[i][j], DIM, wmma::mem_row_major);
}

// ---------------------------------------------------------------------------
// Attention: BQ=128 per CTA, 8 warps, double-buffered K/V via cp.async.
// Exact reference recurrence: o = (alpha*o + P@V) / l_new every iteration.
// ---------------------------------------------------------------------------
#define ATT_SMEM ((128*72 + 2*64*72 + 2*64*72 + 128*72 + 128*64 + 256) * 4)

__global__ __launch_bounds__(256) void attn_kernel()
{
    extern __shared__ float smf[];
    float* Qs  = smf;                 // 128 x 72
    float* Ks0 = Qs  + 128*72;        // 64 x 72
    float* Ks1 = Ks0 + 64*72;
    float* Vs0 = Ks1 + 64*72;
    float* Vs1 = Vs0 + 64*72;
    float* Ss  = Vs1 + 64*72;         // 128 x 72
    float* Os  = Ss  + 128*72;        // 128 x 64
    float* alpha_s = Os + 128*64;     // 128
    float* inv_s   = alpha_s + 128;   // 128

    float* Ks[2] = {Ks0, Ks1};
    float* Vs[2] = {Vs0, Vs1};

    const int tid = threadIdx.x, wid = tid >> 5, lane = tid & 31;
    const int qb = blockIdx.x, h = blockIdx.y, b = blockIdx.z;
    const float scale = 0.125f;
    const int r0 = wid * 16;

    const float* Qg  = g_Q + ((size_t)((b << 4) + h) * SS + qb * 128) * DD;
    const float* Kg0 = g_K + (size_t)((b << 4) + h) * SS * DD;
    const float* Vg0 = g_V + (size_t)((b << 4) + h) * SS * DD;

    auto issueKV = [&](int j, int buf) {
        const float* Kg = Kg0 + (size_t)j * 4096;
        const float* Vg = Vg0 + (size_t)j * 4096;
#pragma unroll
        for (int i = tid; i < 1024; i += 256) {
            int r = i >> 4, c = (i & 15) << 2;
            cp16(Ks[buf] + r*72 + c, Kg + r*DD + c);
        }
#pragma unroll
        for (int i = tid; i < 1024; i += 256) {
            int r = i >> 4, c = (i & 15) << 2;
            cp16(Vs[buf] + r*72 + c, Vg + r*DD + c);
        }
    };

    issueKV(0, 0); cp_commit();

#pragma unroll
    for (int i = tid; i < 2048; i += 256) {    // Q tile 128x64
        int r = i >> 4, c = (i & 15) << 2;
        *(float4*)(Qs + r*72 + c) = *(const float4*)(Qg + r*DD + c);
    }
#pragma unroll
    for (int i = tid; i < 8192; i += 256) Os[i] = 0.f;

    const int row   = wid * 16 + (lane >> 1);
    const int cbase = (lane & 1) * 32;
    float mrun = -INFINITY, lrun = 0.f;

    for (int j = 0; j < 32; j++) {
        const int buf = j & 1;
        if (j + 1 < 32) { issueKV(j + 1, buf ^ 1); cp_commit(); cp_wait<1>(); }
        else            { cp_wait<0>(); }
        __syncthreads();

        // S = scale * Q @ K^T  (warp owns 16 rows)
        {
            wmma::fragment<wmma::accumulator,16,16,8,float> sacc[4];
#pragma unroll
            for (int n = 0; n < 4; n++) wmma::fill_fragment(sacc[n], 0.f);
#pragma unroll
            for (int kk = 0; kk < 8; kk++) {
                wmma::fragment<wmma::matrix_a,16,16,8,wmma::precision::tf32,wmma::row_major> af;
                wmma::load_matrix_sync(af, Qs + r0*72 + kk*8, 72);
                frag_to_tf32(af);
#pragma unroll
                for (int n = 0; n < 4; n++) {
                    wmma::fragment<wmma::matrix_b,16,16,8,wmma::precision::tf32,wmma::col_major> bfr;
                    wmma::load_matrix_sync(bfr, Ks[buf] + (n*16)*72 + kk*8, 72);
                    frag_to_tf32(bfr);
                    wmma::mma_sync(sacc[n], af, bfr, sacc[n]);
                }
            }
#pragma unroll
            for (int n = 0; n < 4; n++) {
#pragma unroll
                for (int t = 0; t < sacc[n].num_elements; t++) sacc[n].x[t] *= scale;
                wmma::store_matrix_sync(Ss + r0*72 + n*16, sacc[n], 72, wmma::mem_row_major);
            }
        }
        __syncwarp();

        // Online softmax (warp-local rows; 2 lanes per row)
        {
            float* srow = Ss + row*72 + cbase;
            float mx = -INFINITY;
#pragma unroll
            for (int c = 0; c < 32; c++) mx = fmaxf(mx, srow[c]);
            mx = fmaxf(mx, __shfl_xor_sync(0xffffffffu, mx, 1));
            float mnew = fmaxf(mrun, mx);
            float sum = 0.f;
#pragma unroll
            for (int c = 0; c < 32; c++) {
                float p = __expf(srow[c] - mnew);
                srow[c] = p;
                sum += p;
            }
            sum += __shfl_xor_sync(0xffffffffu, sum, 1);
            float alpha = __expf(mrun - mnew);
            float lnew = alpha * lrun + sum;
            if ((lane & 1) == 0) { alpha_s[row] = alpha; inv_s[row] = 1.f / lnew; }
            mrun = mnew; lrun = lnew;
        }
        __syncwarp();

        // PV = P @ V (warp-local rows), staged into Ss
        {
            wmma::fragment<wmma::accumulator,16,16,8,float> pacc[4];
#pragma unroll
            for (int n = 0; n < 4; n++) wmma::fill_fragment(pacc[n], 0.f);
#pragma unroll
            for (int kk = 0; kk < 8; kk++) {
                wmma::fragment<wmma::matrix_a,16,16,8,wmma::precision::tf32,wmma::row_major> af;
                wmma::load_matrix_sync(af, Ss + r0*72 + kk*8, 72);
                frag_to_tf32(af);
#pragma unroll
                for (int n = 0; n < 4; n++) {
                    wmma::fragment<wmma::matrix_b,16,16,8,wmma::precision::tf32,wmma::row_major> bfr;
                    wmma::load_matrix_sync(bfr, Vs[buf] + (kk*8)*72 + n*16, 72);
                    frag_to_tf32(bfr);
                    wmma::mma_sync(pacc[n], af, bfr, pacc[n]);
                }
            }
#pragma unroll
            for (int n = 0; n < 4; n++)
                wmma::store_matrix_sync(Ss + r0*72 + n*16, pacc[n], 72, wmma::mem_row_major);
        }
        __syncthreads();

        // o = (alpha*o + PV) / l_new
#pragma unroll
        for (int i = tid; i < 8192; i += 256) {
            int r = i >> 6, c = i & 63;
            Os[i] = (alpha_s[r] * Os[i] + Ss[r*72 + c]) * inv_s[r];
        }
        __syncthreads();
    }

    float* Og = g_O + ((size_t)(b * SS + qb * 128)) * DIM + h * DD;
#pragma unroll
    for (int i = tid; i < 2048; i += 256) {
        int r = i >> 4, c = (i & 15) << 2;
        *(float4*)(Og + (size_t)r*DIM + c) = *(const float4*)(Os + r*DD + c);
    }
}

// ---------------------------------------------------------------------------
extern "C" void kernel_launch(void* const* d_in, const int* in_sizes, int n_in,
                              void* d_out, int out_size)
{
    const float* x  = (const float*)d_in[0];
    const float* Wq = (const float*)d_in[1];
    const float* Wk = (const float*)d_in[2];
    const float* Wv = (const float*)d_in[3];
    const float* Wo = (const float*)d_in[4];

    cudaFuncSetAttribute(attn_kernel, cudaFuncAttributeMaxDynamicSharedMemorySize, ATT_SMEM);

    qkv_kernel<<<dim3(8, 32, 3), 256>>>(x, Wq, Wk, Wv);
    attn_kernel<<<dim3(16, 16, 2), 256, ATT_SMEM>>>();
    oproj_kernel<<<dim3(8, 32), 256>>>(Wo, (float*)d_out);
}

// round 3
// speedup vs baseline: 2.5743x; 2.5743x over previous
#include <cuda_runtime.h>
#include <cuda_fp16.h>
#include <mma.h>
#include <math.h>

using namespace nvcuda;

#define BB 2
#define SS 2048
#define HH 16
#define DD 64
#define DIM 1024
#define MROWS (BB*SS)

// fp16 staging (device globals; no allocs allowed)
__device__ __align__(16) __half g_x16[MROWS*DIM];
__device__ __align__(16) __half g_Wq16[DIM*DIM];
__device__ __align__(16) __half g_Wk16[DIM*DIM];
__device__ __align__(16) __half g_Wv16[DIM*DIM];
__device__ __align__(16) __half g_Wo16[DIM*DIM];
__device__ __align__(16) __half g_Q16[BB*HH*SS*DD];   // (B,H,S,D)
__device__ __align__(16) __half g_K16[BB*HH*SS*DD];
__device__ __align__(16) __half g_V16[BB*HH*SS*DD];
__device__ __align__(16) __half g_O16[MROWS*DIM];     // (B,S,H*D)

// ---------------- helpers ----------------
__device__ __forceinline__ void cp16(void* s, const void* g) {
    unsigned saddr = (unsigned)__cvta_generic_to_shared(s);
    asm volatile("cp.async.cg.shared.global [%0], [%1], 16;\n" :: "r"(saddr), "l"(g));
}
__device__ __forceinline__ void cp_commit() { asm volatile("cp.async.commit_group;\n"); }
template<int N> __device__ __forceinline__ void cp_wait() {
    asm volatile("cp.async.wait_group %0;\n" :: "n"(N));
}

// exp on FMA/ALU pipes (avoids MUFU bottleneck). rel err ~1e-7.
__device__ __forceinline__ float fast_exp(float x) {
    x = fmaxf(x, -87.0f);                       // handles -inf, avoids denormal scale
    float z  = x * 1.4426950408889634f;         // log2(e)
    float zf = floorf(z);
    float f  = z - zf;                          // f in [0,1)
    int   n  = (int)zf;
    float r  = 1.535336188319500e-4f;
    r = fmaf(r, f, 1.339887440266574e-3f);
    r = fmaf(r, f, 9.618437357674640e-3f);
    r = fmaf(r, f, 5.550332471162809e-2f);
    r = fmaf(r, f, 2.402264791363012e-1f);
    r = fmaf(r, f, 6.931472028550421e-1f);
    r = fmaf(r, f, 1.0f);                       // r = 2^f in [1,2)
    return __int_as_float(__float_as_int(r) + (n << 23));
}

// fp32 -> fp16 conversion (vectorized)
__global__ __launch_bounds__(256) void f2h_kernel(const float2* __restrict__ src,
                                                  __half2* __restrict__ dst, int n2) {
    int i = blockIdx.x * blockDim.x + threadIdx.x;
    if (i < n2) { float2 v = src[i]; dst[i] = __floats2half2_rn(v.x, v.y); }
}

// ---------------------------------------------------------------------------
// Projection GEMM: 128x128 tile, 256 threads, fp16 inputs, fp32 accum.
// K-chunk 64, cp.async double-buffered. Warp grid 4x2, warp tile 32x64.
// ---------------------------------------------------------------------------
#define LDA 72     // halves (64 + 8 pad), row pitch 144B (16B-aligned)
#define LDB 136    // halves (128 + 8 pad), row pitch 272B
#define KC  64
#define QKV_SMEM (2*128*LDA*2 + 2*KC*LDB*2)   // 71680 bytes

struct ProjAcc { wmma::fragment<wmma::accumulator,16,16,16,float> acc[2][4]; };

__device__ __forceinline__ void proj_mainloop16(
    const __half* __restrict__ X, const __half* __restrict__ W,
    int m0, int n0, int tid, int wm, int wn, char* smem, ProjAcc& P)
{
    __half* As[2] = { (__half*)smem,                (__half*)smem + 128*LDA };
    __half* Bs[2] = { (__half*)smem + 2*128*LDA,    (__half*)smem + 2*128*LDA + KC*LDB };

#pragma unroll
    for (int i = 0; i < 2; i++)
#pragma unroll
        for (int j = 0; j < 4; j++) wmma::fill_fragment(P.acc[i][j], 0.f);

    auto issue = [&](int k0, int buf) {
#pragma unroll
        for (int i = tid; i < 1024; i += 256) {            // A: 128 x 64 half
            int r = i >> 3, c = (i & 7) << 3;
            cp16(As[buf] + r*LDA + c, X + (size_t)(m0 + r)*DIM + k0 + c);
        }
#pragma unroll
        for (int i = tid; i < 1024; i += 256) {            // B: 64 x 128 half
            int r = i >> 4, c = (i & 15) << 3;
            cp16(Bs[buf] + r*LDB + c, W + (size_t)(k0 + r)*DIM + n0 + c);
        }
    };

    issue(0, 0); cp_commit();

    for (int it = 0; it < DIM/KC; it++) {
        int buf = it & 1;
        if (it + 1 < DIM/KC) { issue((it+1)*KC, buf ^ 1); cp_commit(); cp_wait<1>(); }
        else                 { cp_wait<0>(); }
        __syncthreads();

#pragma unroll
        for (int kk = 0; kk < KC/16; kk++) {
            wmma::fragment<wmma::matrix_a,16,16,16,__half,wmma::row_major> a[2];
#pragma unroll
            for (int i = 0; i < 2; i++)
                wmma::load_matrix_sync(a[i], As[buf] + (wm*32 + i*16)*LDA + kk*16, LDA);
#pragma unroll
            for (int j = 0; j < 4; j++) {
                wmma::fragment<wmma::matrix_b,16,16,16,__half,wmma::row_major> bfr;
                wmma::load_matrix_sync(bfr, Bs[buf] + (kk*16)*LDB + wn*64 + j*16, LDB);
#pragma unroll
                for (int i = 0; i < 2; i++)
                    wmma::mma_sync(P.acc[i][j], a[i], bfr, P.acc[i][j]);
            }
        }
        __syncthreads();
    }
}

// QKV: C = x16 @ W16, scattered into half (B,H,S,D). N-tile 128 = 2 heads.
__global__ __launch_bounds__(256,2) void qkv16_kernel()
{
    extern __shared__ __align__(16) char smem[];

    const __half* W; __half* out;
    if (blockIdx.z == 0)      { W = g_Wq16; out = g_Q16; }
    else if (blockIdx.z == 1) { W = g_Wk16; out = g_K16; }
    else                      { W = g_Wv16; out = g_V16; }

    const int tid = threadIdx.x, wid = tid >> 5, wm = wid >> 1, wn = wid & 1;
    const int m0 = blockIdx.y * 128, n0 = blockIdx.x * 128;

    ProjAcc P;
    proj_mainloop16(g_x16, W, m0, n0, tid, wm, wn, smem, P);

    // Stage fp32 tile in smem, then convert+scatter to half (B,H,S,D)
    float* St = (float*)smem;        // 128 x 132 floats = 67584 B <= 71680
    __syncthreads();
#pragma unroll
    for (int i = 0; i < 2; i++)
#pragma unroll
        for (int j = 0; j < 4; j++)
            wmma::store_matrix_sync(St + (wm*32 + i*16)*132 + wn*64 + j*16,
                                    P.acc[i][j], 132, wmma::mem_row_major);
    __syncthreads();

    const int bb = m0 >> 11, s0 = m0 & 2047;
#pragma unroll
    for (int i = tid; i < 4096; i += 256) {
        int r = i >> 5, c = (i & 31) << 2;          // 4 cols per thread
        int h = (n0 >> 6) + (c >> 6), cc = c & 63;
        __half* dst = out + ((size_t)((bb << 4) + h) * SS + s0 + r) * DD + cc;
        float* s = St + r*132 + c;
        *(__half2*)(dst)     = __floats2half2_rn(s[0], s[1]);
        *(__half2*)(dst + 2) = __floats2half2_rn(s[2], s[3]);
    }
}

// O projection: d_out(fp32) = g_O16 @ Wo16
__global__ __launch_bounds__(256,2) void oproj16_kernel(float* __restrict__ C)
{
    extern __shared__ __align__(16) char smem[];
    const int tid = threadIdx.x, wid = tid >> 5, wm = wid >> 1, wn = wid & 1;
    const int m0 = blockIdx.y * 128, n0 = blockIdx.x * 128;

    ProjAcc P;
    proj_mainloop16(g_O16, g_Wo16, m0, n0, tid, wm, wn, smem, P);

    float* base = C + (size_t)(m0 + wm*32) * DIM + n0 + wn*64;
#pragma unroll
    for (int i = 0; i < 2; i++)
#pragma unroll
        for (int j = 0; j < 4; j++)
            wmma::store_matrix_sync(base + (size_t)(i*16)*DIM + j*16,
                                    P.acc[i][j], DIM, wmma::mem_row_major);
}

// ---------------------------------------------------------------------------
// Attention: BQ=64, 128 threads (warp = 16 q-rows), fp16 mma, fp32 softmax.
// Exact reference recurrence: o = (alpha*o + P@V)/l_new EVERY iteration.
// ---------------------------------------------------------------------------
// smem byte offsets
#define A_QS   0                      // half 64x72
#define A_KS0  9216
#define A_KS1  18432
#define A_VS0  27648
#define A_VS1  36864
#define A_PS   46080                  // half 64x72 (P for PV mma)
#define A_SS   55296                  // float 64x72 (scores / PV staging)
#define A_OS   73728                  // float 64x64
#define A_ALPHA 90112                 // float 64
#define A_INV  90368                  // float 64
#define ATT_SMEM 90624

__global__ __launch_bounds__(128,2) void attn16_kernel()
{
    extern __shared__ __align__(16) char smem[];
    __half* Qs = (__half*)(smem + A_QS);
    __half* Ks[2] = { (__half*)(smem + A_KS0), (__half*)(smem + A_KS1) };
    __half* Vs[2] = { (__half*)(smem + A_VS0), (__half*)(smem + A_VS1) };
    __half* Ps = (__half*)(smem + A_PS);
    float*  Ss = (float*)(smem + A_SS);
    float*  Os = (float*)(smem + A_OS);
    float*  alpha_s = (float*)(smem + A_ALPHA);
    float*  inv_s   = (float*)(smem + A_INV);

    const int tid = threadIdx.x, wid = tid >> 5, lane = tid & 31;
    const int qb = blockIdx.x, h = blockIdx.y, b = blockIdx.z;
    const float scale = 0.125f;
    const int r0 = wid * 16;

    const __half* Qg  = g_Q16 + ((size_t)((b << 4) + h) * SS + qb * 64) * DD;
    const __half* Kg0 = g_K16 + (size_t)((b << 4) + h) * SS * DD;
    const __half* Vg0 = g_V16 + (size_t)((b << 4) + h) * SS * DD;

    auto issueKV = [&](int j, int buf) {
        const __half* Kg = Kg0 + (size_t)j * (64*DD);
        const __half* Vg = Vg0 + (size_t)j * (64*DD);
#pragma unroll
        for (int i = tid; i < 512; i += 128) {
            int r = i >> 3, c = (i & 7) << 3;
            cp16(Ks[buf] + r*72 + c, Kg + r*DD + c);
            cp16(Vs[buf] + r*72 + c, Vg + r*DD + c);
        }
    };

    issueKV(0, 0); cp_commit();

#pragma unroll
    for (int i = tid; i < 512; i += 128) {       // Q tile 64x64 half
        int r = i >> 3, c = (i & 7) << 3;
        *(uint4*)(Qs + r*72 + c) = *(const uint4*)(Qg + r*DD + c);
    }
#pragma unroll
    for (int i = tid; i < 4096; i += 128) Os[i] = 0.f;

    const int row   = wid * 16 + (lane >> 1);    // 2 lanes per row
    const int cbase = (lane & 1) * 32;
    float mrun = -INFINITY, lrun = 0.f;

    for (int j = 0; j < SS/64; j++) {
        const int buf = j & 1;
        if (j + 1 < SS/64) { issueKV(j + 1, buf ^ 1); cp_commit(); cp_wait<1>(); }
        else               { cp_wait<0>(); }
        __syncthreads();

        // S = scale * Q @ K^T (warp owns 16 rows)
        {
            wmma::fragment<wmma::accumulator,16,16,16,float> sacc[4];
#pragma unroll
            for (int n = 0; n < 4; n++) wmma::fill_fragment(sacc[n], 0.f);
#pragma unroll
            for (int kk = 0; kk < 4; kk++) {
                wmma::fragment<wmma::matrix_a,16,16,16,__half,wmma::row_major> af;
                wmma::load_matrix_sync(af, Qs + r0*72 + kk*16, 72);
#pragma unroll
                for (int n = 0; n < 4; n++) {
                    wmma::fragment<wmma::matrix_b,16,16,16,__half,wmma::col_major> bfr;
                    wmma::load_matrix_sync(bfr, Ks[buf] + (n*16)*72 + kk*16, 72);
                    wmma::mma_sync(sacc[n], af, bfr, sacc[n]);
                }
            }
#pragma unroll
            for (int n = 0; n < 4; n++) {
#pragma unroll
                for (int t = 0; t < sacc[n].num_elements; t++) sacc[n].x[t] *= scale;
                wmma::store_matrix_sync(Ss + r0*72 + n*16, sacc[n], 72, wmma::mem_row_major);
            }
        }
        __syncwarp();

        // Online softmax (fp32), write P as fp16 for the PV mma
        {
            const float* srow = Ss + row*72 + cbase;
            __half* prow = Ps + row*72 + cbase;
            float mx = -INFINITY;
#pragma unroll
            for (int c = 0; c < 32; c++) mx = fmaxf(mx, srow[c]);
            mx = fmaxf(mx, __shfl_xor_sync(0xffffffffu, mx, 1));
            float mnew = fmaxf(mrun, mx);
            float sum = 0.f;
#pragma unroll
            for (int c = 0; c < 32; c++) {
                float p = fast_exp(srow[c] - mnew);
                prow[c] = __float2half_rn(p);
                sum += p;
            }
            sum += __shfl_xor_sync(0xffffffffu, sum, 1);
            float alpha = fast_exp(mrun - mnew);
            float lnew = alpha * lrun + sum;
            if ((lane & 1) == 0) { alpha_s[row] = alpha; inv_s[row] = 1.f / lnew; }
            mrun = mnew; lrun = lnew;
        }
        __syncwarp();

        // PV = P @ V (warp-local rows), staged into Ss (fp32)
        {
            wmma::fragment<wmma::accumulator,16,16,16,float> pacc[4];
#pragma unroll
            for (int n = 0; n < 4; n++) wmma::fill_fragment(pacc[n], 0.f);
#pragma unroll
            for (int kk = 0; kk < 4; kk++) {
                wmma::fragment<wmma::matrix_a,16,16,16,__half,wmma::row_major> af;
                wmma::load_matrix_sync(af, Ps + r0*72 + kk*16, 72);
#pragma unroll
                for (int n = 0; n < 4; n++) {
                    wmma::fragment<wmma::matrix_b,16,16,16,__half,wmma::row_major> bfr;
                    wmma::load_matrix_sync(bfr, Vs[buf] + (kk*16)*72 + n*16, 72);
                    wmma::mma_sync(pacc[n], af, bfr, pacc[n]);
                }
            }
#pragma unroll
            for (int n = 0; n < 4; n++)
                wmma::store_matrix_sync(Ss + r0*72 + n*16, pacc[n], 72, wmma::mem_row_major);
        }
        __syncthreads();

        // o = (alpha*o + PV) / l_new
#pragma unroll
        for (int i = tid; i < 4096; i += 128) {
            int r = i >> 6, c = i & 63;
            Os[i] = (alpha_s[r] * Os[i] + Ss[r*72 + c]) * inv_s[r];
        }
        __syncthreads();
    }

    // Write half O into (B, S, H*D)
    __half* Og = g_O16 + ((size_t)(b * SS + qb * 64)) * DIM + h * DD;
#pragma unroll
    for (int i = tid; i < 2048; i += 128) {
        int r = i >> 5, c = (i & 31) << 1;
        *(__half2*)(Og + (size_t)r*DIM + c) = __floats2half2_rn(Os[r*64 + c], Os[r*64 + c + 1]);
    }
}

// ---------------------------------------------------------------------------
extern "C" void kernel_launch(void* const* d_in, const int* in_sizes, int n_in,
                              void* d_out, int out_size)
{
    const float* x  = (const float*)d_in[0];
    const float* Wq = (const float*)d_in[1];
    const float* Wk = (const float*)d_in[2];
    const float* Wv = (const float*)d_in[3];
    const float* Wo = (const float*)d_in[4];

    static bool attr_done = false;
    if (!attr_done) {
        cudaFuncSetAttribute(qkv16_kernel,  cudaFuncAttributeMaxDynamicSharedMemorySize, QKV_SMEM);
        cudaFuncSetAttribute(oproj16_kernel,cudaFuncAttributeMaxDynamicSharedMemorySize, QKV_SMEM);
        cudaFuncSetAttribute(attn16_kernel, cudaFuncAttributeMaxDynamicSharedMemorySize, ATT_SMEM);
        attr_done = true;
    }

    __half2 *dx, *dwq, *dwk, *dwv, *dwo;
    cudaGetSymbolAddress((void**)&dx,  g_x16);
    cudaGetSymbolAddress((void**)&dwq, g_Wq16);
    cudaGetSymbolAddress((void**)&dwk, g_Wk16);
    cudaGetSymbolAddress((void**)&dwv, g_Wv16);
    cudaGetSymbolAddress((void**)&dwo, g_Wo16);

    const int nx2 = MROWS*DIM/2, nw2 = DIM*DIM/2;
    f2h_kernel<<<(nx2+255)/256, 256>>>((const float2*)x,  dx,  nx2);
    f2h_kernel<<<(nw2+255)/256, 256>>>((const float2*)Wq, dwq, nw2);
    f2h_kernel<<<(nw2+255)/256, 256>>>((const float2*)Wk, dwk, nw2);
    f2h_kernel<<<(nw2+255)/256, 256>>>((const float2*)Wv, dwv, nw2);
    f2h_kernel<<<(nw2+255)/256, 256>>>((const float2*)Wo, dwo, nw2);

    qkv16_kernel<<<dim3(8, 32, 3), 256, QKV_SMEM>>>();
    attn16_kernel<<<dim3(32, 16, 2), 128, ATT_SMEM>>>();
    oproj16_kernel<<<dim3(8, 32), 256, QKV_SMEM>>>((float*)d_out);
}